// round 15
// baseline (speedup 1.0000x reference)
#include <cuda_runtime.h>
#include <cuda_fp16.h>
#include <cstdint>

#define NTOK 32768          // B*T = 16*2048
#define INCH 512
#define DLAT 256
#define ZW   768            // 3*DLAT
#define VC   1024
#define VP   1024
#define VT   512
#define VTOT (VC+VP+VT)     // 2560

// output layout: x_recon | vq_loss | idx_c | idx_p | idx_t | zq_c | zq_p | zq_t
#define LOSS_OFF (NTOK*INCH)
#define IDX_OFF  (LOSS_OFF + 1)
#define ZQ_OFF   (IDX_OFF + 3*NTOK)     // ODD offset -> zq stores must be scalar!

#define MARGIN 1.2e-3f
#define CLIST_CAP 192

// -------- scratch (16B-aligned where vector-accessed) --------
__device__ float  g_z[NTOK*ZW];
__device__ __align__(16) __half g_zh[NTOK*ZW];     // fp16(z) for the screen
__device__ __align__(16) __half g_cbh[VTOT*DLAT];  // fp16(cb), concatenated
__device__ float  g_zz[3*NTOK];
__device__ float  g_cc[VTOT];
__device__ __align__(16) __half g_sch[(size_t)NTOK*2560];  // screened r (fp16)
__device__ float  g_tmin[3*NTOK*8];
__device__ int    g_idx[3*NTOK];
__device__ float  g_losspart[3*4096];
__device__ float  g_P[VTOT*INCH];                  // P_h = cb_h @ Wr_h

// ============================================================
// Kernel 1: z = x @ [Wc|Wp|Wt] + b.  Accumulator chain BITWISE
// IDENTICAL to R1/R6/R13; epilogue additionally emits fp16(z).
// ============================================================
__global__ __launch_bounds__(256, 2) void gemm_z_kernel(
    const float* __restrict__ x,
    const float* __restrict__ Wc, const float* __restrict__ Wp, const float* __restrict__ Wt,
    const float* __restrict__ bc, const float* __restrict__ bp, const float* __restrict__ bt)
{
    const int nt  = blockIdx.x;
    const int seg = nt >> 1;
    const float* W  = (seg == 0) ? Wc : (seg == 1 ? Wp : Wt);
    const float* bb = (seg == 0) ? bc : (seg == 1 ? bp : bt);
    const int nseg = (nt & 1) * 128;
    const int m0   = blockIdx.y * 128;

    __shared__ float As[2][8][128];
    __shared__ float Bs[2][8][128];

    const int tid = threadIdx.x;
    const int tx = tid & 15, ty = tid >> 4;

    float acc[8][8];
    #pragma unroll
    for (int i = 0; i < 8; i++)
        #pragma unroll
        for (int j = 0; j < 8; j++) acc[i][j] = 0.f;

    const int arow = tid >> 1;
    const int akq  = (tid & 1) * 4;
    const int bk   = tid >> 5;
    const int bn   = (tid & 31) * 4;

    const float* aptr = x + (size_t)(m0 + arow) * INCH + akq;
    const float* bptr = W + (size_t)bk * DLAT + nseg + bn;

    float4 av = *(const float4*)(aptr);
    float4 bv = *(const float4*)(bptr);
    As[0][akq+0][arow] = av.x; As[0][akq+1][arow] = av.y;
    As[0][akq+2][arow] = av.z; As[0][akq+3][arow] = av.w;
    *(float4*)&Bs[0][bk][bn] = bv;
    __syncthreads();

    for (int c = 0; c < 64; c++) {
        if (c + 1 < 64) {
            av = *(const float4*)(aptr + (c+1)*8);
            bv = *(const float4*)(bptr + (size_t)((c+1)*8) * DLAT);
        }
        const int cur = c & 1;
        #pragma unroll
        for (int kk = 0; kk < 8; kk++) {
            float a[8], b[8];
            *(float4*)&a[0] = *(const float4*)&As[cur][kk][ty*8];
            *(float4*)&a[4] = *(const float4*)&As[cur][kk][ty*8+4];
            *(float4*)&b[0] = *(const float4*)&Bs[cur][kk][tx*8];
            *(float4*)&b[4] = *(const float4*)&Bs[cur][kk][tx*8+4];
            #pragma unroll
            for (int i = 0; i < 8; i++)
                #pragma unroll
                for (int j = 0; j < 8; j++)
                    acc[i][j] = fmaf(a[i], b[j], acc[i][j]);
        }
        if (c + 1 < 64) {
            const int nb = (c + 1) & 1;
            As[nb][akq+0][arow] = av.x; As[nb][akq+1][arow] = av.y;
            As[nb][akq+2][arow] = av.z; As[nb][akq+3][arow] = av.w;
            *(float4*)&Bs[nb][bk][bn] = bv;
        }
        __syncthreads();
    }

    float bj[8];
    #pragma unroll
    for (int j = 0; j < 8; j++) bj[j] = bb[nseg + tx*8 + j];

    #pragma unroll
    for (int i = 0; i < 8; i++) {
        const size_t rowbase = (size_t)(m0 + ty*8 + i) * ZW + nt * 128 + tx*8;
        float* zrow = g_z + rowbase;
        float vv[8];
        #pragma unroll
        for (int j = 0; j < 8; j += 4) {
            float4 v;
            v.x = acc[i][j+0] + bj[j+0];
            v.y = acc[i][j+1] + bj[j+1];
            v.z = acc[i][j+2] + bj[j+2];
            v.w = acc[i][j+3] + bj[j+3];
            *(float4*)&zrow[j] = v;
            vv[j+0] = v.x; vv[j+1] = v.y; vv[j+2] = v.z; vv[j+3] = v.w;
        }
        __half2 hp[4];
        #pragma unroll
        for (int j = 0; j < 4; j++)
            hp[j] = __halves2half2(__float2half_rn(vv[2*j]), __float2half_rn(vv[2*j+1]));
        *(uint4*)(g_zh + rowbase) = *(const uint4*)hp;
    }
}

// ============================================================
// Kernel 2/3: zz (bitwise) and cc (+fp16 copy).
// ============================================================
__global__ void zz_kernel()
{
    const int gid  = blockIdx.x * 8 + (threadIdx.x >> 5);
    const int lane = threadIdx.x & 31;
    const int h = gid / NTOK, tok = gid % NTOK;
    const float* zr = g_z + (size_t)tok * ZW + h * DLAT;
    float s = 0.f;
    #pragma unroll
    for (int q = 0; q < 8; q++) { float v = zr[lane + 32*q]; s = fmaf(v, v, s); }
    #pragma unroll
    for (int off = 16; off; off >>= 1) s += __shfl_down_sync(0xffffffffu, s, off);
    if (lane == 0) g_zz[gid] = s;
}

__global__ void cc_kernel(const float* __restrict__ cbc,
                          const float* __restrict__ cbp,
                          const float* __restrict__ cbt)
{
    const int gid  = blockIdx.x * 8 + (threadIdx.x >> 5);
    const int lane = threadIdx.x & 31;
    const float* row;
    if (gid < VC)           row = cbc + (size_t)gid * DLAT;
    else if (gid < VC + VP) row = cbp + (size_t)(gid - VC) * DLAT;
    else                    row = cbt + (size_t)(gid - VC - VP) * DLAT;
    __half* ch = g_cbh + (size_t)gid * DLAT;
    float s = 0.f;
    #pragma unroll
    for (int q = 0; q < 8; q++) {
        float v = row[lane + 32*q];
        s = fmaf(v, v, s);
        ch[lane + 32*q] = __float2half_rn(v);
    }
    #pragma unroll
    for (int off = 16; off; off >>= 1) s += __shfl_down_sync(0xffffffffu, s, off);
    if (lane == 0) g_cc[gid] = s;
}

// ======================= fp16 mma machinery =======================
__device__ __forceinline__ void mma16(float c[4], const uint32_t a[4], const uint32_t b[2]) {
    asm volatile("mma.sync.aligned.m16n8k16.row.col.f32.f16.f16.f32 "
        "{%0,%1,%2,%3},{%4,%5,%6,%7},{%8,%9},{%0,%1,%2,%3};"
        : "+f"(c[0]), "+f"(c[1]), "+f"(c[2]), "+f"(c[3])
        : "r"(a[0]), "r"(a[1]), "r"(a[2]), "r"(a[3]), "r"(b[0]), "r"(b[1]));
}

#define ROWH 264                 // halves per smem row (256 + 8 pad)
#define TILEH (128*ROWH)         // halves per operand tile
#define SCR_SMEM (2*TILEH*2)     // bytes = 135168

// ============================================================
// Kernel 4: SCREEN — full-K single-buffered smem, ONE sync.
// FIX vs R14: tile copy uses uint4 (128 halves/thread); R14's uint2
// loop moved only 64, leaving the upper half of every row garbage.
// Accumulation order == R13 -> g_sch bitwise identical.
// ============================================================
__global__ __launch_bounds__(256) void screen_h16()
{
    extern __shared__ __half smh[];
    __shared__ float s_cc[128];
    __shared__ float s_min[2][64][4];

    const int tid = threadIdx.x;
    const int bx = blockIdx.x;
    int h, vt;
    if (bx < 8)       { h = 0; vt = bx; }
    else if (bx < 16) { h = 1; vt = bx - 8; }
    else              { h = 2; vt = bx - 16; }
    const int V      = (h == 2) ? 512 : 1024;
    const int ccbase = (h == 0) ? 0 : (h == 1 ? VC : VC + VP);
    const size_t scoff = (h == 0) ? 0 : (h == 1 ? (size_t)NTOK*1024 : (size_t)2*NTOK*1024);
    const int v0 = vt * 128;
    const int m0 = blockIdx.y * 128;

    if (tid < 128) s_cc[tid] = g_cc[ccbase + v0 + tid];

    // ---- load full-K tiles: each thread copies 128 halves per operand ----
    {
        const int lrow = tid >> 1;
        const int hoff = (tid & 1) * 128;       // halves
        const __half* asrc = g_zh + (size_t)(m0 + lrow) * ZW + h * DLAT + hoff;
        const __half* bsrc = g_cbh + (size_t)(ccbase + v0 + lrow) * DLAT + hoff;
        __half* adst = smh + lrow * ROWH + hoff;
        __half* bdst = smh + TILEH + lrow * ROWH + hoff;
        #pragma unroll
        for (int q = 0; q < 16; q++) {
            ((uint4*)adst)[q] = ((const uint4*)asrc)[q];
            ((uint4*)bdst)[q] = ((const uint4*)bsrc)[q];
        }
    }
    __syncthreads();

    float C[4][4][4];
    #pragma unroll
    for (int i = 0; i < 4; i++)
        #pragma unroll
        for (int j = 0; j < 4; j++)
            #pragma unroll
            for (int k = 0; k < 4; k++) C[i][j][k] = 0.f;

    const int lane = tid & 31, wid = tid >> 5;
    const int wm = wid >> 2, wn = wid & 3;
    const int g = lane >> 2, tg = lane & 3;

    const __half* Ab = smh;
    const __half* Bb = smh + TILEH;

    for (int c = 0; c < 8; c++) {               // 8 K-chunks of 32 halves
        #pragma unroll
        for (int kk = 0; kk < 2; kk++) {
            const int kb = c * 32 + kk * 16 + 2 * tg;
            uint32_t ah[4][4], bh[4][2];
            #pragma unroll
            for (int ms = 0; ms < 4; ms++) {
                const int r = wm*64 + ms*16 + g;
                ah[ms][0] = *(const uint32_t*)&Ab[r*ROWH + kb];
                ah[ms][1] = *(const uint32_t*)&Ab[(r+8)*ROWH + kb];
                ah[ms][2] = *(const uint32_t*)&Ab[r*ROWH + kb + 8];
                ah[ms][3] = *(const uint32_t*)&Ab[(r+8)*ROWH + kb + 8];
            }
            #pragma unroll
            for (int ns = 0; ns < 4; ns++) {
                const int n = wn*32 + ns*8 + g;
                bh[ns][0] = *(const uint32_t*)&Bb[n*ROWH + kb];
                bh[ns][1] = *(const uint32_t*)&Bb[n*ROWH + kb + 8];
            }
            #pragma unroll
            for (int ms = 0; ms < 4; ms++)
                #pragma unroll
                for (int ns = 0; ns < 4; ns++) mma16(C[ms][ns], ah[ms], bh[ns]);
        }
    }

    #pragma unroll
    for (int ms = 0; ms < 4; ms++) {
        #pragma unroll
        for (int half = 0; half < 2; half++) {
            const int orow = wm*64 + ms*16 + g + half*8;
            float rmin = 3.402823466e38f;
            #pragma unroll
            for (int ns = 0; ns < 4; ns++) {
                const int col = wn*32 + ns*8 + tg*2;
                float r0 = fmaf(-2.f, C[ms][ns][half*2+0], s_cc[col]);
                float r1 = fmaf(-2.f, C[ms][ns][half*2+1], s_cc[col+1]);
                __half q0 = __float2half_rn(r0);
                __half q1 = __float2half_rn(r1);
                *(__half2*)(g_sch + scoff + (size_t)(m0 + orow) * V + v0 + col) =
                    __halves2half2(q0, q1);
                rmin = fminf(rmin, fminf(__half2float(q0), __half2float(q1)));
            }
            #pragma unroll
            for (int o = 1; o < 4; o <<= 1)
                rmin = fminf(rmin, __shfl_xor_sync(0xffffffffu, rmin, o));
            if (tg == 0) s_min[wm][ms*16 + g + half*8][wn] = rmin;
        }
    }
    __syncthreads();
    if (tid < 128) {
        const int wm2 = tid >> 6, row = tid & 63;
        float m = fminf(fminf(s_min[wm2][row][0], s_min[wm2][row][1]),
                        fminf(s_min[wm2][row][2], s_min[wm2][row][3]));
        g_tmin[((size_t)h * NTOK + m0 + wm2*64 + row) * 8 + vt] = m;
    }
}

// ============================================================
// Kernel 5: RESCORE+MERGE (unchanged from R13)
// ============================================================
__global__ __launch_bounds__(256) void rescore_kernel(
    const float* __restrict__ cbc, const float* __restrict__ cbp,
    const float* __restrict__ cbt, float* __restrict__ out)
{
    __shared__ float zs[8][256];
    __shared__ int   clist[8][CLIST_CAP];
    __shared__ float s_l[8];

    const int h    = blockIdx.y;
    const int warp = threadIdx.x >> 5;
    const int lane = threadIdx.x & 31;
    const int tok  = blockIdx.x * 8 + warp;
    const int V      = (h == 2) ? VT : 1024;
    const int nvt    = (h == 2) ? 4 : 8;
    const int ccbase = (h == 0) ? 0 : (h == 1 ? VC : VC + VP);
    const size_t scoff = (h == 0) ? 0 : (h == 1 ? (size_t)NTOK*1024 : (size_t)2*NTOK*1024);
    const float* cb = (h == 0) ? cbc : (h == 1 ? cbp : cbt);
    const size_t ht = (size_t)h * NTOK + tok;

    const __half2* base2 = (const __half2*)(g_sch + scoff + (size_t)tok * V);

    float m = 3.402823466e38f;
    if (lane < nvt) m = g_tmin[ht * 8 + lane];
    #pragma unroll
    for (int o = 16; o; o >>= 1) m = fminf(m, __shfl_xor_sync(0xffffffffu, m, o));
    const float thr = m + MARGIN;

    const float* zrow = g_z + (size_t)tok * ZW + h * DLAT;
    #pragma unroll
    for (int q = 0; q < 8; q++) zs[warp][lane + 32*q] = zrow[lane + 32*q];
    __syncwarp();

    int cnt = 0;
    for (int i0 = 0; i0 < V; i0 += 64) {
        __half2 hv = base2[(i0 >> 1) + lane];
        float r0 = __low2float(hv), r1 = __high2float(hv);
        bool c0 = (r0 <= thr), c1 = (r1 <= thr);
        unsigned b0 = __ballot_sync(0xffffffffu, c0);
        unsigned b1 = __ballot_sync(0xffffffffu, c1);
        unsigned mask = (1u << lane) - 1;
        int pre = cnt + __popc(b0 & mask) + __popc(b1 & mask);
        if (c0) { if (pre < CLIST_CAP) clist[warp][pre] = i0 + 2*lane; }
        if (c1) { int p = pre + (c0 ? 1 : 0); if (p < CLIST_CAP) clist[warp][p] = i0 + 2*lane + 1; }
        cnt += __popc(b0) + __popc(b1);
    }
    if (cnt > CLIST_CAP) cnt = CLIST_CAP;
    if (cnt == 0) { if (lane == 0) clist[warp][0] = 0; cnt = 1; }
    __syncwarp();

    const float zz = g_zz[ht];
    float bs = 3.402823466e38f; int bv = 0x7fffffff;
    for (int ci = lane; ci < cnt; ci += 32) {
        const int v = clist[warp][ci];
        const float* cr = cb + (size_t)v * DLAT;
        float acc = 0.f;
        #pragma unroll 8
        for (int k = 0; k < 256; k++) acc = fmaf(zs[warp][k], cr[k], acc);
        const float sc = fmaf(-2.f, acc, zz + g_cc[ccbase + v]);
        if (sc < bs || (sc == bs && v < bv)) { bs = sc; bv = v; }
    }
    #pragma unroll
    for (int o = 16; o; o >>= 1) {
        float ob = __shfl_xor_sync(0xffffffffu, bs, o);
        int   ov = __shfl_xor_sync(0xffffffffu, bv, o);
        if (ob < bs || (ob == bs && ov < bv)) { bs = ob; bv = ov; }
    }
    if (lane == 0) {
        g_idx[ht] = bv;
        out[IDX_OFF + ht] = (float)bv;
    }

    const float* cr = cb + (size_t)bv * DLAT;
    float lsum = 0.f;
    #pragma unroll
    for (int q = 0; q < 8; q++) {
        const int k = lane + 32*q;
        const float zv = zs[warp][k];
        const float cv = cr[k];
        const float zqv = zv + (cv - zv);
        out[ZQ_OFF + ht * DLAT + k] = zqv;
        const float d = zv - zqv;
        lsum = fmaf(d, d, lsum);
    }
    #pragma unroll
    for (int o = 16; o; o >>= 1) lsum += __shfl_down_sync(0xffffffffu, lsum, o);
    if (lane == 0) s_l[warp] = lsum;
    __syncthreads();
    if (threadIdx.x == 0) {
        float s = s_l[0];
        #pragma unroll
        for (int w = 1; w < 8; w++) s += s_l[w];
        g_losspart[h * 4096 + blockIdx.x] = s;
    }
}

// ============================================================
// Kernel 6: loss finalize (unchanged)
// ============================================================
__global__ void loss_kernel(float* __restrict__ out)
{
    __shared__ float sh[256];
    __shared__ float mh[3];
    const int tid = threadIdx.x;
    for (int h = 0; h < 3; h++) {
        float s = 0.f;
        for (int i = tid; i < 4096; i += 256) s += g_losspart[h*4096 + i];
        sh[tid] = s;
        __syncthreads();
        for (int off = 128; off; off >>= 1) {
            if (tid < off) sh[tid] += sh[tid + off];
            __syncthreads();
        }
        if (tid == 0) mh[h] = sh[0] / 8388608.0f;
        __syncthreads();
    }
    if (tid == 0) {
        float L = (mh[0] + mh[1] + mh[2]) / 3.0f;
        out[LOSS_OFF] = fmaf(0.25f, L, L);
    }
}

// ============================================================
// Kernel 7: PPROJ — P_h = cb_h @ Wr_h (unchanged)
// ============================================================
__global__ __launch_bounds__(256) void pproj_kernel(
    const float* __restrict__ cbc, const float* __restrict__ cbp,
    const float* __restrict__ cbt, const float* __restrict__ Wr)
{
    __shared__ float As[64][17];
    __shared__ float Bs[16][64];

    const int m0 = blockIdx.x * 64;
    const int n0 = blockIdx.y * 64;
    const int tid = threadIdx.x;
    const int tx = tid & 15, ty = tid >> 4;

    const float* cb; int mloc, kbase;
    if (m0 < VC)           { cb = cbc; mloc = m0;            kbase = 0;   }
    else if (m0 < VC + VP) { cb = cbp; mloc = m0 - VC;       kbase = 256; }
    else                   { cb = cbt; mloc = m0 - VC - VP;  kbase = 512; }

    float acc[4][4];
    #pragma unroll
    for (int i = 0; i < 4; i++)
        #pragma unroll
        for (int j = 0; j < 4; j++) acc[i][j] = 0.f;

    const int arow = tid >> 2, akc = (tid & 3) * 4;
    const int bkr  = tid >> 4, bnc = (tid & 15) * 4;

    for (int k0 = 0; k0 < DLAT; k0 += 16) {
        float4 av = *(const float4*)(cb + (size_t)(mloc + arow) * DLAT + k0 + akc);
        float4 bvv = *(const float4*)(Wr + (size_t)(kbase + k0 + bkr) * INCH + n0 + bnc);
        As[arow][akc+0] = av.x; As[arow][akc+1] = av.y;
        As[arow][akc+2] = av.z; As[arow][akc+3] = av.w;
        *(float4*)&Bs[bkr][bnc] = bvv;
        __syncthreads();
        #pragma unroll
        for (int k = 0; k < 16; k++) {
            float a[4], b[4];
            #pragma unroll
            for (int i = 0; i < 4; i++) a[i] = As[ty*4 + i][k];
            *(float4*)&b[0] = *(const float4*)&Bs[k][tx*4];
            #pragma unroll
            for (int i = 0; i < 4; i++)
                #pragma unroll
                for (int j = 0; j < 4; j++)
                    acc[i][j] = fmaf(a[i], b[j], acc[i][j]);
        }
        __syncthreads();
    }

    #pragma unroll
    for (int i = 0; i < 4; i++)
        *(float4*)(g_P + (size_t)(m0 + ty*4 + i) * INCH + n0 + tx*4) =
            make_float4(acc[i][0], acc[i][1], acc[i][2], acc[i][3]);
}

// ============================================================
// Kernel 8: GATHER-RECON (unchanged)
// ============================================================
__global__ __launch_bounds__(256) void gather_recon_kernel(
    const float* __restrict__ br, float* __restrict__ out)
{
    __shared__ float sbr[INCH];
    const int tid = threadIdx.x;
    #pragma unroll
    for (int q = 0; q < 2; q++) sbr[tid + q*256] = br[tid + q*256];
    __syncthreads();

    const int slot = tid >> 7;
    const int c4   = (tid & 127) * 4;
    const int tok  = blockIdx.x * 2 + slot;

    const int ic = g_idx[tok];
    const int ip = g_idx[NTOK + tok];
    const int it = g_idx[2*NTOK + tok];

    float4 pc = *(const float4*)(g_P + (size_t)ic * INCH + c4);
    float4 pp = *(const float4*)(g_P + (size_t)(VC + ip) * INCH + c4);
    float4 pt = *(const float4*)(g_P + (size_t)(VC + VP + it) * INCH + c4);

    float4 r;
    r.x = pc.x + pp.x + pt.x + sbr[c4+0];
    r.y = pc.y + pp.y + pt.y + sbr[c4+1];
    r.z = pc.z + pp.z + pt.z + sbr[c4+2];
    r.w = pc.w + pp.w + pt.w + sbr[c4+3];
    *(float4*)(out + (size_t)tok * INCH + c4) = r;
}

// ============================================================
extern "C" void kernel_launch(void* const* d_in, const int* in_sizes, int n_in,
                              void* d_out, int out_size)
{
    (void)in_sizes; (void)n_in; (void)out_size;
    const float* x   = (const float*)d_in[0];
    const float* Wc  = (const float*)d_in[1];
    const float* bc  = (const float*)d_in[2];
    const float* Wp  = (const float*)d_in[3];
    const float* bp  = (const float*)d_in[4];
    const float* Wt  = (const float*)d_in[5];
    const float* bt  = (const float*)d_in[6];
    const float* cbc = (const float*)d_in[7];
    const float* cbp = (const float*)d_in[8];
    const float* cbt = (const float*)d_in[9];
    const float* Wr  = (const float*)d_in[10];
    const float* br  = (const float*)d_in[11];
    float* out = (float*)d_out;

    cudaFuncSetAttribute(screen_h16, cudaFuncAttributeMaxDynamicSharedMemorySize, SCR_SMEM);

    pproj_kernel<<<dim3(VTOT/64, INCH/64), 256>>>(cbc, cbp, cbt, Wr);
    gemm_z_kernel<<<dim3(6, NTOK/128), 256>>>(x, Wc, Wp, Wt, bc, bp, bt);
    zz_kernel<<<(3*NTOK)/8, 256>>>();
    cc_kernel<<<VTOT/8, 256>>>(cbc, cbp, cbt);
    screen_h16<<<dim3(20, NTOK/128), 256, SCR_SMEM>>>();
    rescore_kernel<<<dim3(NTOK/8, 3), 256>>>(cbc, cbp, cbt, out);
    loss_kernel<<<1, 256>>>(out);
    gather_recon_kernel<<<NTOK/2, 256>>>(br, out);
}

// round 16
// speedup vs baseline: 1.1202x; 1.1202x over previous
#include <cuda_runtime.h>
#include <cuda_fp16.h>
#include <cstdint>

#define NTOK 32768          // B*T = 16*2048
#define INCH 512
#define DLAT 256
#define ZW   768            // 3*DLAT
#define VC   1024
#define VP   1024
#define VT   512
#define VTOT (VC+VP+VT)     // 2560

// output layout: x_recon | vq_loss | idx_c | idx_p | idx_t | zq_c | zq_p | zq_t
#define LOSS_OFF (NTOK*INCH)
#define IDX_OFF  (LOSS_OFF + 1)
#define ZQ_OFF   (IDX_OFF + 3*NTOK)     // ODD offset -> zq stores must be scalar!

#define MARGIN 1.2e-3f
#define CLIST_CAP 192

// -------- scratch (16B-aligned where vector-accessed) --------
__device__ float  g_z[NTOK*ZW];
__device__ __align__(16) __half g_zh[NTOK*ZW];     // fp16(z) for the screen
__device__ __align__(16) __half g_cbh[VTOT*DLAT];  // fp16(cb), concatenated
__device__ float  g_zz[3*NTOK];
__device__ float  g_cc[VTOT];
__device__ __align__(16) __half g_sch[(size_t)NTOK*2560];  // screened r (fp16)
__device__ float  g_tmin[3*NTOK*8];
__device__ int    g_idx[3*NTOK];
__device__ float  g_losspart[3*4096];
__device__ float  g_P[VTOT*INCH];                  // P_h = cb_h @ Wr_h

// ============================================================
// Kernel 1: z = x @ [Wc|Wp|Wt] + b.  Accumulator chain BITWISE
// IDENTICAL to R1/R6/R13; epilogue additionally emits fp16(z)
// (pure extra store under the FFMA-bound shadow; zz no longer writes it).
// ============================================================
__global__ __launch_bounds__(256, 2) void gemm_z_kernel(
    const float* __restrict__ x,
    const float* __restrict__ Wc, const float* __restrict__ Wp, const float* __restrict__ Wt,
    const float* __restrict__ bc, const float* __restrict__ bp, const float* __restrict__ bt)
{
    const int nt  = blockIdx.x;
    const int seg = nt >> 1;
    const float* W  = (seg == 0) ? Wc : (seg == 1 ? Wp : Wt);
    const float* bb = (seg == 0) ? bc : (seg == 1 ? bp : bt);
    const int nseg = (nt & 1) * 128;
    const int m0   = blockIdx.y * 128;

    __shared__ float As[2][8][128];
    __shared__ float Bs[2][8][128];

    const int tid = threadIdx.x;
    const int tx = tid & 15, ty = tid >> 4;

    float acc[8][8];
    #pragma unroll
    for (int i = 0; i < 8; i++)
        #pragma unroll
        for (int j = 0; j < 8; j++) acc[i][j] = 0.f;

    const int arow = tid >> 1;
    const int akq  = (tid & 1) * 4;
    const int bk   = tid >> 5;
    const int bn   = (tid & 31) * 4;

    const float* aptr = x + (size_t)(m0 + arow) * INCH + akq;
    const float* bptr = W + (size_t)bk * DLAT + nseg + bn;

    float4 av = *(const float4*)(aptr);
    float4 bv = *(const float4*)(bptr);
    As[0][akq+0][arow] = av.x; As[0][akq+1][arow] = av.y;
    As[0][akq+2][arow] = av.z; As[0][akq+3][arow] = av.w;
    *(float4*)&Bs[0][bk][bn] = bv;
    __syncthreads();

    for (int c = 0; c < 64; c++) {
        if (c + 1 < 64) {
            av = *(const float4*)(aptr + (c+1)*8);
            bv = *(const float4*)(bptr + (size_t)((c+1)*8) * DLAT);
        }
        const int cur = c & 1;
        #pragma unroll
        for (int kk = 0; kk < 8; kk++) {
            float a[8], b[8];
            *(float4*)&a[0] = *(const float4*)&As[cur][kk][ty*8];
            *(float4*)&a[4] = *(const float4*)&As[cur][kk][ty*8+4];
            *(float4*)&b[0] = *(const float4*)&Bs[cur][kk][tx*8];
            *(float4*)&b[4] = *(const float4*)&Bs[cur][kk][tx*8+4];
            #pragma unroll
            for (int i = 0; i < 8; i++)
                #pragma unroll
                for (int j = 0; j < 8; j++)
                    acc[i][j] = fmaf(a[i], b[j], acc[i][j]);
        }
        if (c + 1 < 64) {
            const int nb = (c + 1) & 1;
            As[nb][akq+0][arow] = av.x; As[nb][akq+1][arow] = av.y;
            As[nb][akq+2][arow] = av.z; As[nb][akq+3][arow] = av.w;
            *(float4*)&Bs[nb][bk][bn] = bv;
        }
        __syncthreads();
    }

    float bj[8];
    #pragma unroll
    for (int j = 0; j < 8; j++) bj[j] = bb[nseg + tx*8 + j];

    #pragma unroll
    for (int i = 0; i < 8; i++) {
        const size_t rowbase = (size_t)(m0 + ty*8 + i) * ZW + nt * 128 + tx*8;
        float* zrow = g_z + rowbase;
        float vv[8];
        #pragma unroll
        for (int j = 0; j < 8; j += 4) {
            float4 v;
            v.x = acc[i][j+0] + bj[j+0];
            v.y = acc[i][j+1] + bj[j+1];
            v.z = acc[i][j+2] + bj[j+2];
            v.w = acc[i][j+3] + bj[j+3];
            *(float4*)&zrow[j] = v;
            vv[j+0] = v.x; vv[j+1] = v.y; vv[j+2] = v.z; vv[j+3] = v.w;
        }
        __half2 hp[4];
        #pragma unroll
        for (int j = 0; j < 4; j++)
            hp[j] = __halves2half2(__float2half_rn(vv[2*j]), __float2half_rn(vv[2*j+1]));
        *(uint4*)(g_zh + rowbase) = *(const uint4*)hp;
    }
}

// ============================================================
// Kernel 2/3: zz (pure bitwise reduction) and cc (+fp16 copy).
// ============================================================
__global__ void zz_kernel()
{
    const int gid  = blockIdx.x * 8 + (threadIdx.x >> 5);
    const int lane = threadIdx.x & 31;
    const int h = gid / NTOK, tok = gid % NTOK;
    const float* zr = g_z + (size_t)tok * ZW + h * DLAT;
    float s = 0.f;
    #pragma unroll
    for (int q = 0; q < 8; q++) { float v = zr[lane + 32*q]; s = fmaf(v, v, s); }
    #pragma unroll
    for (int off = 16; off; off >>= 1) s += __shfl_down_sync(0xffffffffu, s, off);
    if (lane == 0) g_zz[gid] = s;
}

__global__ void cc_kernel(const float* __restrict__ cbc,
                          const float* __restrict__ cbp,
                          const float* __restrict__ cbt)
{
    const int gid  = blockIdx.x * 8 + (threadIdx.x >> 5);
    const int lane = threadIdx.x & 31;
    const float* row;
    if (gid < VC)           row = cbc + (size_t)gid * DLAT;
    else if (gid < VC + VP) row = cbp + (size_t)(gid - VC) * DLAT;
    else                    row = cbt + (size_t)(gid - VC - VP) * DLAT;
    __half* ch = g_cbh + (size_t)gid * DLAT;
    float s = 0.f;
    #pragma unroll
    for (int q = 0; q < 8; q++) {
        float v = row[lane + 32*q];
        s = fmaf(v, v, s);
        ch[lane + 32*q] = __float2half_rn(v);
    }
    #pragma unroll
    for (int off = 16; off; off >>= 1) s += __shfl_down_sync(0xffffffffu, s, off);
    if (lane == 0) g_cc[gid] = s;
}

// ======================= fp16 mma machinery =======================
__device__ __forceinline__ void mma16(float c[4], const uint32_t a[4], const uint32_t b[2]) {
    asm volatile("mma.sync.aligned.m16n8k16.row.col.f32.f16.f16.f32 "
        "{%0,%1,%2,%3},{%4,%5,%6,%7},{%8,%9},{%0,%1,%2,%3};"
        : "+f"(c[0]), "+f"(c[1]), "+f"(c[2]), "+f"(c[3])
        : "r"(a[0]), "r"(a[1]), "r"(a[2]), "r"(a[3]), "r"(b[0]), "r"(b[1]));
}

#define KCH  32                  // halves per K-chunk
#define PADH 40                  // halves per smem row
#define ASTG (128*PADH)          // halves per operand per stage
#define SSTGH (2*ASTG)           // halves per stage (A then B)
#define SCR_SMEM (2*SSTGH*2)     // bytes = 40960

// ============================================================
// Kernel 4: SCREEN — R13's known-good double-buffered form (40 KB,
// high occupancy): fused all-heads fp16 m16n8k16, register-staged.
// ============================================================
__global__ __launch_bounds__(256) void screen_h16()
{
    extern __shared__ __half smh[];
    __shared__ float s_cc[128];
    __shared__ float s_min[2][64][4];

    const int tid = threadIdx.x;
    const int bx = blockIdx.x;
    int h, vt;
    if (bx < 8)       { h = 0; vt = bx; }
    else if (bx < 16) { h = 1; vt = bx - 8; }
    else              { h = 2; vt = bx - 16; }
    const int V      = (h == 2) ? 512 : 1024;
    const int ccbase = (h == 0) ? 0 : (h == 1 ? VC : VC + VP);
    const size_t scoff = (h == 0) ? 0 : (h == 1 ? (size_t)NTOK*1024 : (size_t)2*NTOK*1024);
    const int v0 = vt * 128;
    const int m0 = blockIdx.y * 128;

    if (tid < 128) s_cc[tid] = g_cc[ccbase + v0 + tid];

    float C[4][4][4];
    #pragma unroll
    for (int i = 0; i < 4; i++)
        #pragma unroll
        for (int j = 0; j < 4; j++)
            #pragma unroll
            for (int k = 0; k < 4; k++) C[i][j][k] = 0.f;

    const int lrow = tid >> 1;
    const int h16  = (tid & 1) * 16;

    uint4 ra[2], rb[2];
    auto g2r = [&](int c) {
        const __half* asrc = g_zh + (size_t)(m0 + lrow) * ZW + h * DLAT + c * KCH + h16;
        ra[0] = *(const uint4*)asrc;
        ra[1] = *(const uint4*)(asrc + 8);
        const __half* bsrc = g_cbh + (size_t)(ccbase + v0 + lrow) * DLAT + c * KCH + h16;
        rb[0] = *(const uint4*)bsrc;
        rb[1] = *(const uint4*)(bsrc + 8);
    };
    auto r2s = [&](int s) {
        __half* base = smh + s * SSTGH;
        *(uint4*)(base + lrow * PADH + h16)            = ra[0];
        *(uint4*)(base + lrow * PADH + h16 + 8)        = ra[1];
        *(uint4*)(base + ASTG + lrow * PADH + h16)     = rb[0];
        *(uint4*)(base + ASTG + lrow * PADH + h16 + 8) = rb[1];
    };

    const int lane = tid & 31, wid = tid >> 5;
    const int wm = wid >> 2, wn = wid & 3;
    const int g = lane >> 2, tg = lane & 3;

    g2r(0); r2s(0); __syncthreads();
    const int NC = DLAT / KCH;   // 8
    for (int c = 0; c < NC; c++) {
        if (c + 1 < NC) g2r(c + 1);
        const __half* base = smh + (c & 1) * SSTGH;
        #pragma unroll
        for (int kk = 0; kk < 2; kk++) {
            const int kb = kk * 16 + 2 * tg;
            uint32_t ah[4][4], bh[4][2];
            #pragma unroll
            for (int ms = 0; ms < 4; ms++) {
                const int r = wm*64 + ms*16 + g;
                ah[ms][0] = *(const uint32_t*)&base[r*PADH + kb];
                ah[ms][1] = *(const uint32_t*)&base[(r+8)*PADH + kb];
                ah[ms][2] = *(const uint32_t*)&base[r*PADH + kb + 8];
                ah[ms][3] = *(const uint32_t*)&base[(r+8)*PADH + kb + 8];
            }
            #pragma unroll
            for (int ns = 0; ns < 4; ns++) {
                const int n = wn*32 + ns*8 + g;
                bh[ns][0] = *(const uint32_t*)&base[ASTG + n*PADH + kb];
                bh[ns][1] = *(const uint32_t*)&base[ASTG + n*PADH + kb + 8];
            }
            #pragma unroll
            for (int ms = 0; ms < 4; ms++)
                #pragma unroll
                for (int ns = 0; ns < 4; ns++) mma16(C[ms][ns], ah[ms], bh[ns]);
        }
        __syncthreads();
        if (c + 1 < NC) { r2s((c + 1) & 1); __syncthreads(); }
    }

    #pragma unroll
    for (int ms = 0; ms < 4; ms++) {
        #pragma unroll
        for (int half = 0; half < 2; half++) {
            const int orow = wm*64 + ms*16 + g + half*8;
            float rmin = 3.402823466e38f;
            #pragma unroll
            for (int ns = 0; ns < 4; ns++) {
                const int col = wn*32 + ns*8 + tg*2;
                float r0 = fmaf(-2.f, C[ms][ns][half*2+0], s_cc[col]);
                float r1 = fmaf(-2.f, C[ms][ns][half*2+1], s_cc[col+1]);
                __half q0 = __float2half_rn(r0);
                __half q1 = __float2half_rn(r1);
                *(__half2*)(g_sch + scoff + (size_t)(m0 + orow) * V + v0 + col) =
                    __halves2half2(q0, q1);
                rmin = fminf(rmin, fminf(__half2float(q0), __half2float(q1)));
            }
            #pragma unroll
            for (int o = 1; o < 4; o <<= 1)
                rmin = fminf(rmin, __shfl_xor_sync(0xffffffffu, rmin, o));
            if (tg == 0) s_min[wm][ms*16 + g + half*8][wn] = rmin;
        }
    }
    __syncthreads();
    if (tid < 128) {
        const int wm2 = tid >> 6, row = tid & 63;
        float m = fminf(fminf(s_min[wm2][row][0], s_min[wm2][row][1]),
                        fminf(s_min[wm2][row][2], s_min[wm2][row][3]));
        g_tmin[((size_t)h * NTOK + m0 + wm2*64 + row) * 8 + vt] = m;
    }
}

// ============================================================
// Kernel 5: RESCORE+MERGE (unchanged from R13)
// ============================================================
__global__ __launch_bounds__(256) void rescore_kernel(
    const float* __restrict__ cbc, const float* __restrict__ cbp,
    const float* __restrict__ cbt, float* __restrict__ out)
{
    __shared__ float zs[8][256];
    __shared__ int   clist[8][CLIST_CAP];
    __shared__ float s_l[8];

    const int h    = blockIdx.y;
    const int warp = threadIdx.x >> 5;
    const int lane = threadIdx.x & 31;
    const int tok  = blockIdx.x * 8 + warp;
    const int V      = (h == 2) ? VT : 1024;
    const int nvt    = (h == 2) ? 4 : 8;
    const int ccbase = (h == 0) ? 0 : (h == 1 ? VC : VC + VP);
    const size_t scoff = (h == 0) ? 0 : (h == 1 ? (size_t)NTOK*1024 : (size_t)2*NTOK*1024);
    const float* cb = (h == 0) ? cbc : (h == 1 ? cbp : cbt);
    const size_t ht = (size_t)h * NTOK + tok;

    const __half2* base2 = (const __half2*)(g_sch + scoff + (size_t)tok * V);

    float m = 3.402823466e38f;
    if (lane < nvt) m = g_tmin[ht * 8 + lane];
    #pragma unroll
    for (int o = 16; o; o >>= 1) m = fminf(m, __shfl_xor_sync(0xffffffffu, m, o));
    const float thr = m + MARGIN;

    const float* zrow = g_z + (size_t)tok * ZW + h * DLAT;
    #pragma unroll
    for (int q = 0; q < 8; q++) zs[warp][lane + 32*q] = zrow[lane + 32*q];
    __syncwarp();

    int cnt = 0;
    for (int i0 = 0; i0 < V; i0 += 64) {
        __half2 hv = base2[(i0 >> 1) + lane];
        float r0 = __low2float(hv), r1 = __high2float(hv);
        bool c0 = (r0 <= thr), c1 = (r1 <= thr);
        unsigned b0 = __ballot_sync(0xffffffffu, c0);
        unsigned b1 = __ballot_sync(0xffffffffu, c1);
        unsigned mask = (1u << lane) - 1;
        int pre = cnt + __popc(b0 & mask) + __popc(b1 & mask);
        if (c0) { if (pre < CLIST_CAP) clist[warp][pre] = i0 + 2*lane; }
        if (c1) { int p = pre + (c0 ? 1 : 0); if (p < CLIST_CAP) clist[warp][p] = i0 + 2*lane + 1; }
        cnt += __popc(b0) + __popc(b1);
    }
    if (cnt > CLIST_CAP) cnt = CLIST_CAP;
    if (cnt == 0) { if (lane == 0) clist[warp][0] = 0; cnt = 1; }
    __syncwarp();

    const float zz = g_zz[ht];
    float bs = 3.402823466e38f; int bv = 0x7fffffff;
    for (int ci = lane; ci < cnt; ci += 32) {
        const int v = clist[warp][ci];
        const float* cr = cb + (size_t)v * DLAT;
        float acc = 0.f;
        #pragma unroll 8
        for (int k = 0; k < 256; k++) acc = fmaf(zs[warp][k], cr[k], acc);
        const float sc = fmaf(-2.f, acc, zz + g_cc[ccbase + v]);
        if (sc < bs || (sc == bs && v < bv)) { bs = sc; bv = v; }
    }
    #pragma unroll
    for (int o = 16; o; o >>= 1) {
        float ob = __shfl_xor_sync(0xffffffffu, bs, o);
        int   ov = __shfl_xor_sync(0xffffffffu, bv, o);
        if (ob < bs || (ob == bs && ov < bv)) { bs = ob; bv = ov; }
    }
    if (lane == 0) {
        g_idx[ht] = bv;
        out[IDX_OFF + ht] = (float)bv;
    }

    const float* cr = cb + (size_t)bv * DLAT;
    float lsum = 0.f;
    #pragma unroll
    for (int q = 0; q < 8; q++) {
        const int k = lane + 32*q;
        const float zv = zs[warp][k];
        const float cv = cr[k];
        const float zqv = zv + (cv - zv);
        out[ZQ_OFF + ht * DLAT + k] = zqv;
        const float d = zv - zqv;
        lsum = fmaf(d, d, lsum);
    }
    #pragma unroll
    for (int o = 16; o; o >>= 1) lsum += __shfl_down_sync(0xffffffffu, lsum, o);
    if (lane == 0) s_l[warp] = lsum;
    __syncthreads();
    if (threadIdx.x == 0) {
        float s = s_l[0];
        #pragma unroll
        for (int w = 1; w < 8; w++) s += s_l[w];
        g_losspart[h * 4096 + blockIdx.x] = s;
    }
}

// ============================================================
// Kernel 6: loss finalize (unchanged)
// ============================================================
__global__ void loss_kernel(float* __restrict__ out)
{
    __shared__ float sh[256];
    __shared__ float mh[3];
    const int tid = threadIdx.x;
    for (int h = 0; h < 3; h++) {
        float s = 0.f;
        for (int i = tid; i < 4096; i += 256) s += g_losspart[h*4096 + i];
        sh[tid] = s;
        __syncthreads();
        for (int off = 128; off; off >>= 1) {
            if (tid < off) sh[tid] += sh[tid + off];
            __syncthreads();
        }
        if (tid == 0) mh[h] = sh[0] / 8388608.0f;
        __syncthreads();
    }
    if (tid == 0) {
        float L = (mh[0] + mh[1] + mh[2]) / 3.0f;
        out[LOSS_OFF] = fmaf(0.25f, L, L);
    }
}

// ============================================================
// Kernel 7: PPROJ — P_h = cb_h @ Wr_h (unchanged)
// ============================================================
__global__ __launch_bounds__(256) void pproj_kernel(
    const float* __restrict__ cbc, const float* __restrict__ cbp,
    const float* __restrict__ cbt, const float* __restrict__ Wr)
{
    __shared__ float As[64][17];
    __shared__ float Bs[16][64];

    const int m0 = blockIdx.x * 64;
    const int n0 = blockIdx.y * 64;
    const int tid = threadIdx.x;
    const int tx = tid & 15, ty = tid >> 4;

    const float* cb; int mloc, kbase;
    if (m0 < VC)           { cb = cbc; mloc = m0;            kbase = 0;   }
    else if (m0 < VC + VP) { cb = cbp; mloc = m0 - VC;       kbase = 256; }
    else                   { cb = cbt; mloc = m0 - VC - VP;  kbase = 512; }

    float acc[4][4];
    #pragma unroll
    for (int i = 0; i < 4; i++)
        #pragma unroll
        for (int j = 0; j < 4; j++) acc[i][j] = 0.f;

    const int arow = tid >> 2, akc = (tid & 3) * 4;
    const int bkr  = tid >> 4, bnc = (tid & 15) * 4;

    for (int k0 = 0; k0 < DLAT; k0 += 16) {
        float4 av = *(const float4*)(cb + (size_t)(mloc + arow) * DLAT + k0 + akc);
        float4 bvv = *(const float4*)(Wr + (size_t)(kbase + k0 + bkr) * INCH + n0 + bnc);
        As[arow][akc+0] = av.x; As[arow][akc+1] = av.y;
        As[arow][akc+2] = av.z; As[arow][akc+3] = av.w;
        *(float4*)&Bs[bkr][bnc] = bvv;
        __syncthreads();
        #pragma unroll
        for (int k = 0; k < 16; k++) {
            float a[4], b[4];
            #pragma unroll
            for (int i = 0; i < 4; i++) a[i] = As[ty*4 + i][k];
            *(float4*)&b[0] = *(const float4*)&Bs[k][tx*4];
            #pragma unroll
            for (int i = 0; i < 4; i++)
                #pragma unroll
                for (int j = 0; j < 4; j++)
                    acc[i][j] = fmaf(a[i], b[j], acc[i][j]);
        }
        __syncthreads();
    }

    #pragma unroll
    for (int i = 0; i < 4; i++)
        *(float4*)(g_P + (size_t)(m0 + ty*4 + i) * INCH + n0 + tx*4) =
            make_float4(acc[i][0], acc[i][1], acc[i][2], acc[i][3]);
}

// ============================================================
// Kernel 8: GATHER-RECON (unchanged)
// ============================================================
__global__ __launch_bounds__(256) void gather_recon_kernel(
    const float* __restrict__ br, float* __restrict__ out)
{
    __shared__ float sbr[INCH];
    const int tid = threadIdx.x;
    #pragma unroll
    for (int q = 0; q < 2; q++) sbr[tid + q*256] = br[tid + q*256];
    __syncthreads();

    const int slot = tid >> 7;
    const int c4   = (tid & 127) * 4;
    const int tok  = blockIdx.x * 2 + slot;

    const int ic = g_idx[tok];
    const int ip = g_idx[NTOK + tok];
    const int it = g_idx[2*NTOK + tok];

    float4 pc = *(const float4*)(g_P + (size_t)ic * INCH + c4);
    float4 pp = *(const float4*)(g_P + (size_t)(VC + ip) * INCH + c4);
    float4 pt = *(const float4*)(g_P + (size_t)(VC + VP + it) * INCH + c4);

    float4 r;
    r.x = pc.x + pp.x + pt.x + sbr[c4+0];
    r.y = pc.y + pp.y + pt.y + sbr[c4+1];
    r.z = pc.z + pp.z + pt.z + sbr[c4+2];
    r.w = pc.w + pp.w + pt.w + sbr[c4+3];
    *(float4*)(out + (size_t)tok * INCH + c4) = r;
}

// ============================================================
extern "C" void kernel_launch(void* const* d_in, const int* in_sizes, int n_in,
                              void* d_out, int out_size)
{
    (void)in_sizes; (void)n_in; (void)out_size;
    const float* x   = (const float*)d_in[0];
    const float* Wc  = (const float*)d_in[1];
    const float* bc  = (const float*)d_in[2];
    const float* Wp  = (const float*)d_in[3];
    const float* bp  = (const float*)d_in[4];
    const float* Wt  = (const float*)d_in[5];
    const float* bt  = (const float*)d_in[6];
    const float* cbc = (const float*)d_in[7];
    const float* cbp = (const float*)d_in[8];
    const float* cbt = (const float*)d_in[9];
    const float* Wr  = (const float*)d_in[10];
    const float* br  = (const float*)d_in[11];
    float* out = (float*)d_out;

    cudaFuncSetAttribute(screen_h16, cudaFuncAttributeMaxDynamicSharedMemorySize, SCR_SMEM);

    pproj_kernel<<<dim3(VTOT/64, INCH/64), 256>>>(cbc, cbp, cbt, Wr);
    gemm_z_kernel<<<dim3(6, NTOK/128), 256>>>(x, Wc, Wp, Wt, bc, bp, bt);
    zz_kernel<<<(3*NTOK)/8, 256>>>();
    cc_kernel<<<VTOT/8, 256>>>(cbc, cbp, cbt);
    screen_h16<<<dim3(20, NTOK/128), 256, SCR_SMEM>>>();
    rescore_kernel<<<dim3(NTOK/8, 3), 256>>>(cbc, cbp, cbt, out);
    loss_kernel<<<1, 256>>>(out);
    gather_recon_kernel<<<NTOK/2, 256>>>(br, out);
}

// round 17
// speedup vs baseline: 1.1311x; 1.0097x over previous
#include <cuda_runtime.h>
#include <cuda_fp16.h>
#include <cstdint>

#define NTOK 32768          // B*T = 16*2048
#define INCH 512
#define DLAT 256
#define ZW   768            // 3*DLAT
#define VC   1024
#define VP   1024
#define VT   512
#define VTOT (VC+VP+VT)     // 2560

// output layout: x_recon | vq_loss | idx_c | idx_p | idx_t | zq_c | zq_p | zq_t
#define LOSS_OFF (NTOK*INCH)
#define IDX_OFF  (LOSS_OFF + 1)
#define ZQ_OFF   (IDX_OFF + 3*NTOK)     // ODD offset -> zq stores must be scalar!

#define MARGIN 1.2e-3f
#define CLIST_CAP 192

// -------- scratch (16B-aligned where vector-accessed) --------
__device__ float  g_z[NTOK*ZW];
__device__ __align__(16) __half g_zh[NTOK*ZW];     // fp16(z) for the screen
__device__ __align__(16) __half g_cbh[VTOT*DLAT];  // fp16(cb), concatenated
__device__ float  g_zz[3*NTOK];
__device__ float  g_cc[VTOT];
__device__ __align__(16) __half g_sch[(size_t)NTOK*2560];  // screened r (fp16)
__device__ float  g_tmin[3*NTOK*8];
__device__ int    g_idx[3*NTOK];
__device__ float  g_losspart[3*4096];
__device__ float  g_P[VTOT*INCH];                  // P_h = cb_h @ Wr_h

// ============================================================
// Kernel 1: z = x @ [Wc|Wp|Wt] + b.
// RETILED 128x64 (acc 8x4) for 3 CTAs/SM (6 warps/SMSP) + explicit
// fragment double-buffering. Each output's k-ascending fmaf chain and
// the acc+bias adds are UNCHANGED -> z and fp16(z) bitwise identical
// to R16 (tile shape / FFMA interleave are not part of the chain).
// ============================================================
__global__ __launch_bounds__(256, 3) void gemm_z_kernel(
    const float* __restrict__ x,
    const float* __restrict__ Wc, const float* __restrict__ Wp, const float* __restrict__ Wt,
    const float* __restrict__ bc, const float* __restrict__ bp, const float* __restrict__ bt)
{
    const int nt  = blockIdx.x;                 // 0..11: 64-col tile of the 768-wide z
    const int seg = nt >> 2;                    // head
    const float* W  = (seg == 0) ? Wc : (seg == 1 ? Wp : Wt);
    const float* bb = (seg == 0) ? bc : (seg == 1 ? bp : bt);
    const int nseg = (nt & 3) * 64;             // column offset within head
    const int m0   = blockIdx.y * 128;

    __shared__ float As[2][8][128];
    __shared__ float Bs[2][8][64];

    const int tid = threadIdx.x;
    const int tx = tid & 15, ty = tid >> 4;     // 16x16 -> cols tx*4, rows ty*8

    float acc[8][4];
    #pragma unroll
    for (int i = 0; i < 8; i++)
        #pragma unroll
        for (int j = 0; j < 4; j++) acc[i][j] = 0.f;

    const int arow = tid >> 1;
    const int akq  = (tid & 1) * 4;
    const int bk   = tid >> 5;                  // 0..7
    const int bn   = (tid & 31) * 2;            // 0..62

    const float* aptr = x + (size_t)(m0 + arow) * INCH + akq;
    const float* bptr = W + (size_t)bk * DLAT + nseg + bn;

    float4 av = *(const float4*)(aptr);
    float2 bv = *(const float2*)(bptr);
    As[0][akq+0][arow] = av.x; As[0][akq+1][arow] = av.y;
    As[0][akq+2][arow] = av.z; As[0][akq+3][arow] = av.w;
    Bs[0][bk][bn] = bv.x; Bs[0][bk][bn+1] = bv.y;
    __syncthreads();

    for (int c = 0; c < 64; c++) {
        if (c + 1 < 64) {
            av = *(const float4*)(aptr + (c+1)*8);
            bv = *(const float2*)(bptr + (size_t)((c+1)*8) * DLAT);
        }
        const int cur = c & 1;

        // fragment double-buffer over kk
        float af[2][8], bf[2][4];
        *(float4*)&af[0][0] = *(const float4*)&As[cur][0][ty*8];
        *(float4*)&af[0][4] = *(const float4*)&As[cur][0][ty*8+4];
        *(float4*)&bf[0][0] = *(const float4*)&Bs[cur][0][tx*4];

        #pragma unroll
        for (int kk = 0; kk < 8; kk++) {
            const int cb_ = kk & 1, nb_ = (kk + 1) & 1;
            if (kk < 7) {
                *(float4*)&af[nb_][0] = *(const float4*)&As[cur][kk+1][ty*8];
                *(float4*)&af[nb_][4] = *(const float4*)&As[cur][kk+1][ty*8+4];
                *(float4*)&bf[nb_][0] = *(const float4*)&Bs[cur][kk+1][tx*4];
            }
            #pragma unroll
            for (int i = 0; i < 8; i++)
                #pragma unroll
                for (int j = 0; j < 4; j++)
                    acc[i][j] = fmaf(af[cb_][i], bf[cb_][j], acc[i][j]);
        }

        if (c + 1 < 64) {
            const int nb = (c + 1) & 1;
            As[nb][akq+0][arow] = av.x; As[nb][akq+1][arow] = av.y;
            As[nb][akq+2][arow] = av.z; As[nb][akq+3][arow] = av.w;
            Bs[nb][bk][bn] = bv.x; Bs[nb][bk][bn+1] = bv.y;
        }
        __syncthreads();
    }

    float bj[4];
    #pragma unroll
    for (int j = 0; j < 4; j++) bj[j] = bb[nseg + tx*4 + j];

    #pragma unroll
    for (int i = 0; i < 8; i++) {
        const size_t rowbase = (size_t)(m0 + ty*8 + i) * ZW + nt * 64 + tx*4;
        float4 v;
        v.x = acc[i][0] + bj[0];
        v.y = acc[i][1] + bj[1];
        v.z = acc[i][2] + bj[2];
        v.w = acc[i][3] + bj[3];
        *(float4*)(g_z + rowbase) = v;
        __half2 hp[2];
        hp[0] = __halves2half2(__float2half_rn(v.x), __float2half_rn(v.y));
        hp[1] = __halves2half2(__float2half_rn(v.z), __float2half_rn(v.w));
        *(uint2*)(g_zh + rowbase) = *(const uint2*)hp;
    }
}

// ============================================================
// Kernel 2/3: zz (pure bitwise reduction) and cc (+fp16 copy).
// ============================================================
__global__ void zz_kernel()
{
    const int gid  = blockIdx.x * 8 + (threadIdx.x >> 5);
    const int lane = threadIdx.x & 31;
    const int h = gid / NTOK, tok = gid % NTOK;
    const float* zr = g_z + (size_t)tok * ZW + h * DLAT;
    float s = 0.f;
    #pragma unroll
    for (int q = 0; q < 8; q++) { float v = zr[lane + 32*q]; s = fmaf(v, v, s); }
    #pragma unroll
    for (int off = 16; off; off >>= 1) s += __shfl_down_sync(0xffffffffu, s, off);
    if (lane == 0) g_zz[gid] = s;
}

__global__ void cc_kernel(const float* __restrict__ cbc,
                          const float* __restrict__ cbp,
                          const float* __restrict__ cbt)
{
    const int gid  = blockIdx.x * 8 + (threadIdx.x >> 5);
    const int lane = threadIdx.x & 31;
    const float* row;
    if (gid < VC)           row = cbc + (size_t)gid * DLAT;
    else if (gid < VC + VP) row = cbp + (size_t)(gid - VC) * DLAT;
    else                    row = cbt + (size_t)(gid - VC - VP) * DLAT;
    __half* ch = g_cbh + (size_t)gid * DLAT;
    float s = 0.f;
    #pragma unroll
    for (int q = 0; q < 8; q++) {
        float v = row[lane + 32*q];
        s = fmaf(v, v, s);
        ch[lane + 32*q] = __float2half_rn(v);
    }
    #pragma unroll
    for (int off = 16; off; off >>= 1) s += __shfl_down_sync(0xffffffffu, s, off);
    if (lane == 0) g_cc[gid] = s;
}

// ======================= fp16 mma machinery =======================
__device__ __forceinline__ void mma16(float c[4], const uint32_t a[4], const uint32_t b[2]) {
    asm volatile("mma.sync.aligned.m16n8k16.row.col.f32.f16.f16.f32 "
        "{%0,%1,%2,%3},{%4,%5,%6,%7},{%8,%9},{%0,%1,%2,%3};"
        : "+f"(c[0]), "+f"(c[1]), "+f"(c[2]), "+f"(c[3])
        : "r"(a[0]), "r"(a[1]), "r"(a[2]), "r"(a[3]), "r"(b[0]), "r"(b[1]));
}

#define KCH  32                  // halves per K-chunk
#define PADH 40                  // halves per smem row
#define ASTG (128*PADH)          // halves per operand per stage
#define SSTGH (2*ASTG)           // halves per stage (A then B)
#define SCR_SMEM (2*SSTGH*2)     // bytes = 40960

// ============================================================
// Kernel 4: SCREEN — R13/R16's known-good double-buffered form.
// ============================================================
__global__ __launch_bounds__(256) void screen_h16()
{
    extern __shared__ __half smh[];
    __shared__ float s_cc[128];
    __shared__ float s_min[2][64][4];

    const int tid = threadIdx.x;
    const int bx = blockIdx.x;
    int h, vt;
    if (bx < 8)       { h = 0; vt = bx; }
    else if (bx < 16) { h = 1; vt = bx - 8; }
    else              { h = 2; vt = bx - 16; }
    const int V      = (h == 2) ? 512 : 1024;
    const int ccbase = (h == 0) ? 0 : (h == 1 ? VC : VC + VP);
    const size_t scoff = (h == 0) ? 0 : (h == 1 ? (size_t)NTOK*1024 : (size_t)2*NTOK*1024);
    const int v0 = vt * 128;
    const int m0 = blockIdx.y * 128;

    if (tid < 128) s_cc[tid] = g_cc[ccbase + v0 + tid];

    float C[4][4][4];
    #pragma unroll
    for (int i = 0; i < 4; i++)
        #pragma unroll
        for (int j = 0; j < 4; j++)
            #pragma unroll
            for (int k = 0; k < 4; k++) C[i][j][k] = 0.f;

    const int lrow = tid >> 1;
    const int h16  = (tid & 1) * 16;

    uint4 ra[2], rb[2];
    auto g2r = [&](int c) {
        const __half* asrc = g_zh + (size_t)(m0 + lrow) * ZW + h * DLAT + c * KCH + h16;
        ra[0] = *(const uint4*)asrc;
        ra[1] = *(const uint4*)(asrc + 8);
        const __half* bsrc = g_cbh + (size_t)(ccbase + v0 + lrow) * DLAT + c * KCH + h16;
        rb[0] = *(const uint4*)bsrc;
        rb[1] = *(const uint4*)(bsrc + 8);
    };
    auto r2s = [&](int s) {
        __half* base = smh + s * SSTGH;
        *(uint4*)(base + lrow * PADH + h16)            = ra[0];
        *(uint4*)(base + lrow * PADH + h16 + 8)        = ra[1];
        *(uint4*)(base + ASTG + lrow * PADH + h16)     = rb[0];
        *(uint4*)(base + ASTG + lrow * PADH + h16 + 8) = rb[1];
    };

    const int lane = tid & 31, wid = tid >> 5;
    const int wm = wid >> 2, wn = wid & 3;
    const int g = lane >> 2, tg = lane & 3;

    g2r(0); r2s(0); __syncthreads();
    const int NC = DLAT / KCH;   // 8
    for (int c = 0; c < NC; c++) {
        if (c + 1 < NC) g2r(c + 1);
        const __half* base = smh + (c & 1) * SSTGH;
        #pragma unroll
        for (int kk = 0; kk < 2; kk++) {
            const int kb = kk * 16 + 2 * tg;
            uint32_t ah[4][4], bh[4][2];
            #pragma unroll
            for (int ms = 0; ms < 4; ms++) {
                const int r = wm*64 + ms*16 + g;
                ah[ms][0] = *(const uint32_t*)&base[r*PADH + kb];
                ah[ms][1] = *(const uint32_t*)&base[(r+8)*PADH + kb];
                ah[ms][2] = *(const uint32_t*)&base[r*PADH + kb + 8];
                ah[ms][3] = *(const uint32_t*)&base[(r+8)*PADH + kb + 8];
            }
            #pragma unroll
            for (int ns = 0; ns < 4; ns++) {
                const int n = wn*32 + ns*8 + g;
                bh[ns][0] = *(const uint32_t*)&base[ASTG + n*PADH + kb];
                bh[ns][1] = *(const uint32_t*)&base[ASTG + n*PADH + kb + 8];
            }
            #pragma unroll
            for (int ms = 0; ms < 4; ms++)
                #pragma unroll
                for (int ns = 0; ns < 4; ns++) mma16(C[ms][ns], ah[ms], bh[ns]);
        }
        __syncthreads();
        if (c + 1 < NC) { r2s((c + 1) & 1); __syncthreads(); }
    }

    #pragma unroll
    for (int ms = 0; ms < 4; ms++) {
        #pragma unroll
        for (int half = 0; half < 2; half++) {
            const int orow = wm*64 + ms*16 + g + half*8;
            float rmin = 3.402823466e38f;
            #pragma unroll
            for (int ns = 0; ns < 4; ns++) {
                const int col = wn*32 + ns*8 + tg*2;
                float r0 = fmaf(-2.f, C[ms][ns][half*2+0], s_cc[col]);
                float r1 = fmaf(-2.f, C[ms][ns][half*2+1], s_cc[col+1]);
                __half q0 = __float2half_rn(r0);
                __half q1 = __float2half_rn(r1);
                *(__half2*)(g_sch + scoff + (size_t)(m0 + orow) * V + v0 + col) =
                    __halves2half2(q0, q1);
                rmin = fminf(rmin, fminf(__half2float(q0), __half2float(q1)));
            }
            #pragma unroll
            for (int o = 1; o < 4; o <<= 1)
                rmin = fminf(rmin, __shfl_xor_sync(0xffffffffu, rmin, o));
            if (tg == 0) s_min[wm][ms*16 + g + half*8][wn] = rmin;
        }
    }
    __syncthreads();
    if (tid < 128) {
        const int wm2 = tid >> 6, row = tid & 63;
        float m = fminf(fminf(s_min[wm2][row][0], s_min[wm2][row][1]),
                        fminf(s_min[wm2][row][2], s_min[wm2][row][3]));
        g_tmin[((size_t)h * NTOK + m0 + wm2*64 + row) * 8 + vt] = m;
    }
}

// ============================================================
// Kernel 5: RESCORE+MERGE (unchanged from R16)
// ============================================================
__global__ __launch_bounds__(256) void rescore_kernel(
    const float* __restrict__ cbc, const float* __restrict__ cbp,
    const float* __restrict__ cbt, float* __restrict__ out)
{
    __shared__ float zs[8][256];
    __shared__ int   clist[8][CLIST_CAP];
    __shared__ float s_l[8];

    const int h    = blockIdx.y;
    const int warp = threadIdx.x >> 5;
    const int lane = threadIdx.x & 31;
    const int tok  = blockIdx.x * 8 + warp;
    const int V      = (h == 2) ? VT : 1024;
    const int nvt    = (h == 2) ? 4 : 8;
    const int ccbase = (h == 0) ? 0 : (h == 1 ? VC : VC + VP);
    const size_t scoff = (h == 0) ? 0 : (h == 1 ? (size_t)NTOK*1024 : (size_t)2*NTOK*1024);
    const float* cb = (h == 0) ? cbc : (h == 1 ? cbp : cbt);
    const size_t ht = (size_t)h * NTOK + tok;

    const __half2* base2 = (const __half2*)(g_sch + scoff + (size_t)tok * V);

    float m = 3.402823466e38f;
    if (lane < nvt) m = g_tmin[ht * 8 + lane];
    #pragma unroll
    for (int o = 16; o; o >>= 1) m = fminf(m, __shfl_xor_sync(0xffffffffu, m, o));
    const float thr = m + MARGIN;

    const float* zrow = g_z + (size_t)tok * ZW + h * DLAT;
    #pragma unroll
    for (int q = 0; q < 8; q++) zs[warp][lane + 32*q] = zrow[lane + 32*q];
    __syncwarp();

    int cnt = 0;
    for (int i0 = 0; i0 < V; i0 += 64) {
        __half2 hv = base2[(i0 >> 1) + lane];
        float r0 = __low2float(hv), r1 = __high2float(hv);
        bool c0 = (r0 <= thr), c1 = (r1 <= thr);
        unsigned b0 = __ballot_sync(0xffffffffu, c0);
        unsigned b1 = __ballot_sync(0xffffffffu, c1);
        unsigned mask = (1u << lane) - 1;
        int pre = cnt + __popc(b0 & mask) + __popc(b1 & mask);
        if (c0) { if (pre < CLIST_CAP) clist[warp][pre] = i0 + 2*lane; }
        if (c1) { int p = pre + (c0 ? 1 : 0); if (p < CLIST_CAP) clist[warp][p] = i0 + 2*lane + 1; }
        cnt += __popc(b0) + __popc(b1);
    }
    if (cnt > CLIST_CAP) cnt = CLIST_CAP;
    if (cnt == 0) { if (lane == 0) clist[warp][0] = 0; cnt = 1; }
    __syncwarp();

    const float zz = g_zz[ht];
    float bs = 3.402823466e38f; int bv = 0x7fffffff;
    for (int ci = lane; ci < cnt; ci += 32) {
        const int v = clist[warp][ci];
        const float* cr = cb + (size_t)v * DLAT;
        float acc = 0.f;
        #pragma unroll 8
        for (int k = 0; k < 256; k++) acc = fmaf(zs[warp][k], cr[k], acc);
        const float sc = fmaf(-2.f, acc, zz + g_cc[ccbase + v]);
        if (sc < bs || (sc == bs && v < bv)) { bs = sc; bv = v; }
    }
    #pragma unroll
    for (int o = 16; o; o >>= 1) {
        float ob = __shfl_xor_sync(0xffffffffu, bs, o);
        int   ov = __shfl_xor_sync(0xffffffffu, bv, o);
        if (ob < bs || (ob == bs && ov < bv)) { bs = ob; bv = ov; }
    }
    if (lane == 0) {
        g_idx[ht] = bv;
        out[IDX_OFF + ht] = (float)bv;
    }

    const float* cr = cb + (size_t)bv * DLAT;
    float lsum = 0.f;
    #pragma unroll
    for (int q = 0; q < 8; q++) {
        const int k = lane + 32*q;
        const float zv = zs[warp][k];
        const float cv = cr[k];
        const float zqv = zv + (cv - zv);
        out[ZQ_OFF + ht * DLAT + k] = zqv;
        const float d = zv - zqv;
        lsum = fmaf(d, d, lsum);
    }
    #pragma unroll
    for (int o = 16; o; o >>= 1) lsum += __shfl_down_sync(0xffffffffu, lsum, o);
    if (lane == 0) s_l[warp] = lsum;
    __syncthreads();
    if (threadIdx.x == 0) {
        float s = s_l[0];
        #pragma unroll
        for (int w = 1; w < 8; w++) s += s_l[w];
        g_losspart[h * 4096 + blockIdx.x] = s;
    }
}

// ============================================================
// Kernel 6: loss finalize (unchanged)
// ============================================================
__global__ void loss_kernel(float* __restrict__ out)
{
    __shared__ float sh[256];
    __shared__ float mh[3];
    const int tid = threadIdx.x;
    for (int h = 0; h < 3; h++) {
        float s = 0.f;
        for (int i = tid; i < 4096; i += 256) s += g_losspart[h*4096 + i];
        sh[tid] = s;
        __syncthreads();
        for (int off = 128; off; off >>= 1) {
            if (tid < off) sh[tid] += sh[tid + off];
            __syncthreads();
        }
        if (tid == 0) mh[h] = sh[0] / 8388608.0f;
        __syncthreads();
    }
    if (tid == 0) {
        float L = (mh[0] + mh[1] + mh[2]) / 3.0f;
        out[LOSS_OFF] = fmaf(0.25f, L, L);
    }
}

// ============================================================
// Kernel 7: PPROJ — P_h = cb_h @ Wr_h (unchanged)
// ============================================================
__global__ __launch_bounds__(256) void pproj_kernel(
    const float* __restrict__ cbc, const float* __restrict__ cbp,
    const float* __restrict__ cbt, const float* __restrict__ Wr)
{
    __shared__ float As[64][17];
    __shared__ float Bs[16][64];

    const int m0 = blockIdx.x * 64;
    const int n0 = blockIdx.y * 64;
    const int tid = threadIdx.x;
    const int tx = tid & 15, ty = tid >> 4;

    const float* cb; int mloc, kbase;
    if (m0 < VC)           { cb = cbc; mloc = m0;            kbase = 0;   }
    else if (m0 < VC + VP) { cb = cbp; mloc = m0 - VC;       kbase = 256; }
    else                   { cb = cbt; mloc = m0 - VC - VP;  kbase = 512; }

    float acc[4][4];
    #pragma unroll
    for (int i = 0; i < 4; i++)
        #pragma unroll
        for (int j = 0; j < 4; j++) acc[i][j] = 0.f;

    const int arow = tid >> 2, akc = (tid & 3) * 4;
    const int bkr  = tid >> 4, bnc = (tid & 15) * 4;

    for (int k0 = 0; k0 < DLAT; k0 += 16) {
        float4 av = *(const float4*)(cb + (size_t)(mloc + arow) * DLAT + k0 + akc);
        float4 bvv = *(const float4*)(Wr + (size_t)(kbase + k0 + bkr) * INCH + n0 + bnc);
        As[arow][akc+0] = av.x; As[arow][akc+1] = av.y;
        As[arow][akc+2] = av.z; As[arow][akc+3] = av.w;
        *(float4*)&Bs[bkr][bnc] = bvv;
        __syncthreads();
        #pragma unroll
        for (int k = 0; k < 16; k++) {
            float a[4], b[4];
            #pragma unroll
            for (int i = 0; i < 4; i++) a[i] = As[ty*4 + i][k];
            *(float4*)&b[0] = *(const float4*)&Bs[k][tx*4];
            #pragma unroll
            for (int i = 0; i < 4; i++)
                #pragma unroll
                for (int j = 0; j < 4; j++)
                    acc[i][j] = fmaf(a[i], b[j], acc[i][j]);
        }
        __syncthreads();
    }

    #pragma unroll
    for (int i = 0; i < 4; i++)
        *(float4*)(g_P + (size_t)(m0 + ty*4 + i) * INCH + n0 + tx*4) =
            make_float4(acc[i][0], acc[i][1], acc[i][2], acc[i][3]);
}

// ============================================================
// Kernel 8: GATHER-RECON (unchanged)
// ============================================================
__global__ __launch_bounds__(256) void gather_recon_kernel(
    const float* __restrict__ br, float* __restrict__ out)
{
    __shared__ float sbr[INCH];
    const int tid = threadIdx.x;
    #pragma unroll
    for (int q = 0; q < 2; q++) sbr[tid + q*256] = br[tid + q*256];
    __syncthreads();

    const int slot = tid >> 7;
    const int c4   = (tid & 127) * 4;
    const int tok  = blockIdx.x * 2 + slot;

    const int ic = g_idx[tok];
    const int ip = g_idx[NTOK + tok];
    const int it = g_idx[2*NTOK + tok];

    float4 pc = *(const float4*)(g_P + (size_t)ic * INCH + c4);
    float4 pp = *(const float4*)(g_P + (size_t)(VC + ip) * INCH + c4);
    float4 pt = *(const float4*)(g_P + (size_t)(VC + VP + it) * INCH + c4);

    float4 r;
    r.x = pc.x + pp.x + pt.x + sbr[c4+0];
    r.y = pc.y + pp.y + pt.y + sbr[c4+1];
    r.z = pc.z + pp.z + pt.z + sbr[c4+2];
    r.w = pc.w + pp.w + pt.w + sbr[c4+3];
    *(float4*)(out + (size_t)tok * INCH + c4) = r;
}

// ============================================================
extern "C" void kernel_launch(void* const* d_in, const int* in_sizes, int n_in,
                              void* d_out, int out_size)
{
    (void)in_sizes; (void)n_in; (void)out_size;
    const float* x   = (const float*)d_in[0];
    const float* Wc  = (const float*)d_in[1];
    const float* bc  = (const float*)d_in[2];
    const float* Wp  = (const float*)d_in[3];
    const float* bp  = (const float*)d_in[4];
    const float* Wt  = (const float*)d_in[5];
    const float* bt  = (const float*)d_in[6];
    const float* cbc = (const float*)d_in[7];
    const float* cbp = (const float*)d_in[8];
    const float* cbt = (const float*)d_in[9];
    const float* Wr  = (const float*)d_in[10];
    const float* br  = (const float*)d_in[11];
    float* out = (float*)d_out;

    cudaFuncSetAttribute(screen_h16, cudaFuncAttributeMaxDynamicSharedMemorySize, SCR_SMEM);

    pproj_kernel<<<dim3(VTOT/64, INCH/64), 256>>>(cbc, cbp, cbt, Wr);
    gemm_z_kernel<<<dim3(12, NTOK/128), 256>>>(x, Wc, Wp, Wt, bc, bp, bt);
    zz_kernel<<<(3*NTOK)/8, 256>>>();
    cc_kernel<<<VTOT/8, 256>>>(cbc, cbp, cbt);
    screen_h16<<<dim3(20, NTOK/128), 256, SCR_SMEM>>>();
    rescore_kernel<<<dim3(NTOK/8, 3), 256>>>(cbc, cbp, cbt, out);
    loss_kernel<<<1, 256>>>(out);
    gather_recon_kernel<<<NTOK/2, 256>>>(br, out);
}